// round 1
// baseline (speedup 1.0000x reference)
#include <cuda_runtime.h>
#include <math.h>

#define EPS 1e-8f

struct V3 { float x, y, z; };
struct Q4 { float x, y, z, w; };

__device__ __forceinline__ V3 v3(float x, float y, float z) { V3 r; r.x=x; r.y=y; r.z=z; return r; }
__device__ __forceinline__ V3 vadd(V3 a, V3 b) { return v3(a.x+b.x, a.y+b.y, a.z+b.z); }
__device__ __forceinline__ V3 vsub(V3 a, V3 b) { return v3(a.x-b.x, a.y-b.y, a.z-b.z); }
__device__ __forceinline__ V3 vscale(V3 a, float s) { return v3(a.x*s, a.y*s, a.z*s); }
__device__ __forceinline__ float vdot(V3 a, V3 b) { return fmaf(a.x,b.x, fmaf(a.y,b.y, a.z*b.z)); }
__device__ __forceinline__ V3 vcross(V3 a, V3 b) {
    return v3(a.y*b.z - a.z*b.y,
              a.z*b.x - a.x*b.z,
              a.x*b.y - a.y*b.x);
}

__device__ __forceinline__ Q4 qconj(Q4 q) { Q4 r; r.x=-q.x; r.y=-q.y; r.z=-q.z; r.w=q.w; return r; }

__device__ __forceinline__ Q4 qmul(Q4 q, Q4 r) {
    // w = qw*rw - dot(qv, rv) ; v = qw*rv + rw*qv + cross(qv, rv)
    Q4 o;
    V3 qv = v3(q.x,q.y,q.z), rv = v3(r.x,r.y,r.z);
    V3 c = vcross(qv, rv);
    o.x = q.w*r.x + r.w*q.x + c.x;
    o.y = q.w*r.y + r.w*q.y + c.y;
    o.z = q.w*r.z + r.w*q.z + c.z;
    o.w = q.w*r.w - vdot(qv, rv);
    return o;
}

__device__ __forceinline__ V3 qrot(Q4 q, V3 v) {
    V3 qv = v3(q.x,q.y,q.z);
    V3 t = vscale(vcross(qv, v), 2.0f);
    V3 r = vadd(vadd(v, vscale(t, q.w)), vcross(qv, t));
    return r;
}

__device__ __forceinline__ V3 so3_log(Q4 q) {
    V3 v = v3(q.x,q.y,q.z);
    float n2 = vdot(v, v);
    float n = sqrtf(n2);
    float theta = 2.0f * atan2f(n, q.w);
    float k;
    if (n > EPS) {
        k = theta / n;
    } else {
        float wd = (fabsf(q.w) > EPS) ? q.w : 1.0f;
        k = 2.0f / wd;
    }
    return vscale(v, k);
}

// se3_log: returns tau in *tau, phi in *phi
__device__ __forceinline__ void se3_log(V3 t, Q4 q, V3* tau, V3* phi_out) {
    V3 phi = so3_log(q);
    float theta2 = vdot(phi, phi);
    float theta = sqrtf(theta2);
    float coef;
    if (theta < 1e-4f) {
        coef = 1.0f / 12.0f;
    } else {
        float s, c;
        sincosf(theta, &s, &c);
        coef = 1.0f / theta2 - (1.0f + c) / (2.0f * theta * s);
    }
    V3 pxt = vcross(phi, t);
    V3 tau_v = vadd(vsub(t, vscale(pxt, 0.5f)), vscale(vcross(phi, pxt), coef));
    *tau = tau_v;
    *phi_out = phi;
}

__device__ __forceinline__ void load_pose(const float* p, V3* t, Q4* q) {
    t->x = p[0]; t->y = p[1]; t->z = p[2];
    q->x = p[3]; q->y = p[4]; q->z = p[5]; q->w = p[6];
}

// ---------------- Edge kernel: pose-graph residual -----------------
__global__ void edge_kernel(const int* __restrict__ edges,
                            const float* __restrict__ nodes,
                            const float* __restrict__ poses,
                            float* __restrict__ out,
                            int E)
{
    int e = blockIdx.x * blockDim.x + threadIdx.x;
    if (e >= E) return;

    int i1 = edges[2*e + 0];
    int i2 = edges[2*e + 1];

    V3 t1, t2, tp;
    Q4 q1, q2, qp;
    load_pose(nodes + (size_t)i1 * 7, &t1, &q1);
    load_pose(nodes + (size_t)i2 * 7, &t2, &q2);
    load_pose(poses + (size_t)e * 7, &tp, &qp);

    Q4 qi1 = qconj(q1);
    V3 ti1 = vscale(qrot(qi1, t1), -1.0f);
    Q4 qa = qmul(qi1, q2);
    V3 ta = vadd(ti1, qrot(qi1, t2));

    Q4 qip = qconj(qp);
    V3 tip = vscale(qrot(qip, tp), -1.0f);
    Q4 qe = qmul(qip, qa);
    V3 te = vadd(tip, qrot(qip, ta));

    V3 tau, phi;
    se3_log(te, qe, &tau, &phi);

    // L1 = 1.0
    float* o = out + (size_t)e * 6;
    o[0] = tau.x; o[1] = tau.y; o[2] = tau.z;
    o[3] = phi.x; o[4] = phi.y; o[5] = phi.z;
}

// ---------------- Node kernel: IMU residuals -----------------
__global__ void node_kernel(const float* __restrict__ nodes,
                            const float* __restrict__ vels,
                            const float* __restrict__ imu_drots,
                            const float* __restrict__ imu_dtrans,
                            const float* __restrict__ imu_dvels,
                            const float* __restrict__ dts,
                            float* __restrict__ out_adjvel,   // 3 per i, scale L2
                            float* __restrict__ out_imurot,   // 3 per i, scale L3
                            float* __restrict__ out_transvel, // 3 per i, scale L4
                            int M)
{
    int i = blockIdx.x * blockDim.x + threadIdx.x;
    if (i >= M) return;

    V3 t0, t1;
    Q4 q0, q1;
    load_pose(nodes + (size_t)i * 7, &t0, &q0);
    load_pose(nodes + (size_t)(i+1) * 7, &t1, &q1);

    V3 v0 = v3(vels[3*i+0], vels[3*i+1], vels[3*i+2]);
    V3 v1 = v3(vels[3*(i+1)+0], vels[3*(i+1)+1], vels[3*(i+1)+2]);

    // adjvelerr = imu_dvels - (v1 - v0), scale L2 = 0.1
    V3 dv = v3(imu_dvels[3*i+0], imu_dvels[3*i+1], imu_dvels[3*i+2]);
    V3 adj = vsub(dv, vsub(v1, v0));
    out_adjvel[3*i+0] = 0.1f * adj.x;
    out_adjvel[3*i+1] = 0.1f * adj.y;
    out_adjvel[3*i+2] = 0.1f * adj.z;

    // qre = qmul(conj(imu_drots), qmul(conj(q0), q1)), imuroterr = so3_log(qre), L3 = 1.0
    Q4 dr;
    dr.x = imu_drots[4*i+0]; dr.y = imu_drots[4*i+1];
    dr.z = imu_drots[4*i+2]; dr.w = imu_drots[4*i+3];
    Q4 qre = qmul(qconj(dr), qmul(qconj(q0), q1));
    V3 rot = so3_log(qre);
    out_imurot[3*i+0] = rot.x;
    out_imurot[3*i+1] = rot.y;
    out_imurot[3*i+2] = rot.z;

    // transvelerr = t1 - t0 - (v0*dt + imu_dtrans), scale L4 = 0.1
    float dt = dts[i];
    V3 dtr = v3(imu_dtrans[3*i+0], imu_dtrans[3*i+1], imu_dtrans[3*i+2]);
    V3 tv = vsub(vsub(t1, t0), vadd(vscale(v0, dt), dtr));
    out_transvel[3*i+0] = 0.1f * tv.x;
    out_transvel[3*i+1] = 0.1f * tv.y;
    out_transvel[3*i+2] = 0.1f * tv.z;
}

extern "C" void kernel_launch(void* const* d_in, const int* in_sizes, int n_in,
                              void* d_out, int out_size) {
    const int*   edges      = (const int*)  d_in[0];
    const float* nodes      = (const float*)d_in[1];
    const float* vels       = (const float*)d_in[2];
    const float* poses      = (const float*)d_in[3];
    const float* imu_drots  = (const float*)d_in[4];
    const float* imu_dtrans = (const float*)d_in[5];
    const float* imu_dvels  = (const float*)d_in[6];
    const float* dts        = (const float*)d_in[7];

    int E = in_sizes[0] / 2;
    int N = in_sizes[1] / 7;
    int M = N - 1;

    float* out = (float*)d_out;
    float* out_pg       = out;                       // 6E floats
    float* out_adjvel   = out + (size_t)6 * E;       // 3M floats
    float* out_imurot   = out_adjvel + (size_t)3 * M;
    float* out_transvel = out_imurot + (size_t)3 * M;

    const int TPB = 256;
    edge_kernel<<<(E + TPB - 1) / TPB, TPB>>>(edges, nodes, poses, out_pg, E);
    node_kernel<<<(M + TPB - 1) / TPB, TPB>>>(nodes, vels, imu_drots, imu_dtrans,
                                              imu_dvels, dts,
                                              out_adjvel, out_imurot, out_transvel, M);
}

// round 2
// speedup vs baseline: 1.1169x; 1.1169x over previous
#include <cuda_runtime.h>
#include <math.h>

#define EPS 1e-8f

struct V3 { float x, y, z; };
struct Q4 { float x, y, z, w; };

__device__ __forceinline__ V3 v3(float x, float y, float z) { V3 r; r.x=x; r.y=y; r.z=z; return r; }
__device__ __forceinline__ V3 vadd(V3 a, V3 b) { return v3(a.x+b.x, a.y+b.y, a.z+b.z); }
__device__ __forceinline__ V3 vsub(V3 a, V3 b) { return v3(a.x-b.x, a.y-b.y, a.z-b.z); }
__device__ __forceinline__ V3 vscale(V3 a, float s) { return v3(a.x*s, a.y*s, a.z*s); }
__device__ __forceinline__ float vdot(V3 a, V3 b) { return fmaf(a.x,b.x, fmaf(a.y,b.y, a.z*b.z)); }
__device__ __forceinline__ V3 vcross(V3 a, V3 b) {
    return v3(a.y*b.z - a.z*b.y,
              a.z*b.x - a.x*b.z,
              a.x*b.y - a.y*b.x);
}

__device__ __forceinline__ Q4 qconj(Q4 q) { Q4 r; r.x=-q.x; r.y=-q.y; r.z=-q.z; r.w=q.w; return r; }

__device__ __forceinline__ Q4 qmul(Q4 q, Q4 r) {
    Q4 o;
    V3 qv = v3(q.x,q.y,q.z), rv = v3(r.x,r.y,r.z);
    V3 c = vcross(qv, rv);
    o.x = q.w*r.x + r.w*q.x + c.x;
    o.y = q.w*r.y + r.w*q.y + c.y;
    o.z = q.w*r.z + r.w*q.z + c.z;
    o.w = q.w*r.w - vdot(qv, rv);
    return o;
}

__device__ __forceinline__ V3 qrot(Q4 q, V3 v) {
    V3 qv = v3(q.x,q.y,q.z);
    V3 t = vscale(vcross(qv, v), 2.0f);
    return vadd(vadd(v, vscale(t, q.w)), vcross(qv, t));
}

__device__ __forceinline__ V3 so3_log(Q4 q) {
    V3 v = v3(q.x,q.y,q.z);
    float n2 = vdot(v, v);
    float n = sqrtf(n2);
    float theta = 2.0f * atan2f(n, q.w);
    float k;
    if (n > EPS) {
        k = theta / n;
    } else {
        float wd = (fabsf(q.w) > EPS) ? q.w : 1.0f;
        k = 2.0f / wd;
    }
    return vscale(v, k);
}

__device__ __forceinline__ void se3_log(V3 t, Q4 q, V3* tau, V3* phi_out) {
    V3 phi = so3_log(q);
    float theta2 = vdot(phi, phi);
    float theta = sqrtf(theta2);
    float coef;
    if (theta < 1e-4f) {
        coef = 1.0f / 12.0f;
    } else {
        float s, c;
        sincosf(theta, &s, &c);
        coef = 1.0f / theta2 - (1.0f + c) / (2.0f * theta * s);
    }
    V3 pxt = vcross(phi, t);
    *tau = vadd(vsub(t, vscale(pxt, 0.5f)), vscale(vcross(phi, pxt), coef));
    *phi_out = phi;
}

// Load 7-float pose row with scalar loads (random gather path)
__device__ __forceinline__ void load_pose_g(const float* __restrict__ p, V3* t, Q4* q) {
    float a0 = __ldg(p+0), a1 = __ldg(p+1), a2 = __ldg(p+2), a3 = __ldg(p+3);
    float a4 = __ldg(p+4), a5 = __ldg(p+5), a6 = __ldg(p+6);
    t->x = a0; t->y = a1; t->z = a2;
    q->x = a3; q->y = a4; q->z = a5; q->w = a6;
}

__device__ __forceinline__ void edge_compute(V3 t1, Q4 q1, V3 t2, Q4 q2,
                                             V3 tp, Q4 qp, V3* tau, V3* phi) {
    Q4 qi1 = qconj(q1);
    V3 ti1 = vscale(qrot(qi1, t1), -1.0f);
    Q4 qa = qmul(qi1, q2);
    V3 ta = vadd(ti1, qrot(qi1, t2));

    Q4 qip = qconj(qp);
    V3 tip = vscale(qrot(qip, tp), -1.0f);
    Q4 qe = qmul(qip, qa);
    V3 te = vadd(tip, qrot(qip, ta));

    se3_log(te, qe, tau, phi);
}

// ---------------- Fused kernel -----------------
// Blocks [0, edgeBlocks): edge work, 2 edges per thread.
// Blocks [edgeBlocks, edgeBlocks + nodeBlocks): node work, 1 pair per thread.
__global__ __launch_bounds__(256)
void fused_kernel(const int*   __restrict__ edges,
                  const float* __restrict__ nodes,
                  const float* __restrict__ vels,
                  const float* __restrict__ poses,
                  const float* __restrict__ imu_drots,
                  const float* __restrict__ imu_dtrans,
                  const float* __restrict__ imu_dvels,
                  const float* __restrict__ dts,
                  float* __restrict__ out_pg,
                  float* __restrict__ out_adjvel,
                  float* __restrict__ out_imurot,
                  float* __restrict__ out_transvel,
                  int E, int M, int edgeBlocks)
{
    if ((int)blockIdx.x < edgeBlocks) {
        // ---- edge path: thread t handles edges 2t and 2t+1 ----
        int t = blockIdx.x * blockDim.x + threadIdx.x;
        int e0 = 2 * t;
        if (e0 >= E) return;
        bool has2 = (e0 + 1) < E;

        // indices for both edges: int4, 16B-aligned (offset = 16*t bytes)
        int4 idx = *reinterpret_cast<const int4*>(edges + 4 * (size_t)t);
        // guard: if !has2, idx.z/.w may read past — E is even in practice (2E ints given),
        // but protect anyway by clamping below only when used.

        // two pose rows: 14 floats = 7 x float2, 8B-aligned (offset = 56*t bytes)
        const float2* pp = reinterpret_cast<const float2*>(poses + 14 * (size_t)t);
        float2 p0 = pp[0], p1 = pp[1], p2 = pp[2], p3 = pp[3];
        float2 p4 = pp[4], p5 = pp[5], p6 = pp[6];

        // node gathers (4 rows) — issue all loads up front for MLP
        V3 ta1, ta2, tb1, tb2;
        Q4 qa1, qa2, qb1, qb2;
        load_pose_g(nodes + (size_t)idx.x * 7, &ta1, &qa1);
        load_pose_g(nodes + (size_t)idx.y * 7, &ta2, &qa2);
        int i3 = has2 ? idx.z : idx.x;
        int i4 = has2 ? idx.w : idx.y;
        load_pose_g(nodes + (size_t)i3 * 7, &tb1, &qb1);
        load_pose_g(nodes + (size_t)i4 * 7, &tb2, &qb2);

        // unpack pose rows
        V3 tpa = v3(p0.x, p0.y, p1.x);
        Q4 qpa; qpa.x = p1.y; qpa.y = p2.x; qpa.z = p2.y; qpa.w = p3.x;
        V3 tpb = v3(p3.y, p4.x, p4.y);
        Q4 qpb; qpb.x = p5.x; qpb.y = p5.y; qpb.z = p6.x; qpb.w = p6.y;

        V3 tauA, phiA, tauB, phiB;
        edge_compute(ta1, qa1, ta2, qa2, tpa, qpa, &tauA, &phiA);
        edge_compute(tb1, qb1, tb2, qb2, tpb, qpb, &tauB, &phiB);

        // output: 12 floats = 3 x float4, 16B-aligned (offset = 48*t bytes)
        float* o = out_pg + 12 * (size_t)t;
        if (has2) {
            float4 s0 = make_float4(tauA.x, tauA.y, tauA.z, phiA.x);
            float4 s1 = make_float4(phiA.y, phiA.z, tauB.x, tauB.y);
            float4 s2 = make_float4(tauB.z, phiB.x, phiB.y, phiB.z);
            reinterpret_cast<float4*>(o)[0] = s0;
            reinterpret_cast<float4*>(o)[1] = s1;
            reinterpret_cast<float4*>(o)[2] = s2;
        } else {
            o[0]=tauA.x; o[1]=tauA.y; o[2]=tauA.z;
            o[3]=phiA.x; o[4]=phiA.y; o[5]=phiA.z;
        }
    } else {
        // ---- node path ----
        int i = (blockIdx.x - edgeBlocks) * blockDim.x + threadIdx.x;
        if (i >= M) return;

        const float* n0 = nodes + (size_t)i * 7;
        float a0=n0[0], a1=n0[1], a2=n0[2], a3=n0[3], a4=n0[4], a5=n0[5], a6=n0[6];
        float b0=n0[7], b1=n0[8], b2=n0[9], b3=n0[10], b4=n0[11], b5=n0[12], b6=n0[13];

        float v0x=vels[3*i+0], v0y=vels[3*i+1], v0z=vels[3*i+2];
        float v1x=vels[3*i+3], v1y=vels[3*i+4], v1z=vels[3*i+5];

        float4 drq = *reinterpret_cast<const float4*>(imu_drots + 4 * (size_t)i);
        float dvx=imu_dvels[3*i+0], dvy=imu_dvels[3*i+1], dvz=imu_dvels[3*i+2];
        float dtx=imu_dtrans[3*i+0], dty=imu_dtrans[3*i+1], dtz=imu_dtrans[3*i+2];
        float dt = dts[i];

        V3 t0 = v3(a0,a1,a2), t1 = v3(b0,b1,b2);
        Q4 q0; q0.x=a3; q0.y=a4; q0.z=a5; q0.w=a6;
        Q4 q1; q1.x=b3; q1.y=b4; q1.z=b5; q1.w=b6;

        // adjvelerr = imu_dvels - (v1 - v0), L2 = 0.1
        out_adjvel[3*i+0] = 0.1f * (dvx - (v1x - v0x));
        out_adjvel[3*i+1] = 0.1f * (dvy - (v1y - v0y));
        out_adjvel[3*i+2] = 0.1f * (dvz - (v1z - v0z));

        // imuroterr = so3_log(conj(drot) * conj(q0) * q1), L3 = 1.0
        Q4 dr; dr.x=drq.x; dr.y=drq.y; dr.z=drq.z; dr.w=drq.w;
        Q4 qre = qmul(qconj(dr), qmul(qconj(q0), q1));
        V3 rot = so3_log(qre);
        out_imurot[3*i+0] = rot.x;
        out_imurot[3*i+1] = rot.y;
        out_imurot[3*i+2] = rot.z;

        // transvelerr = t1 - t0 - (v0*dt + imu_dtrans), L4 = 0.1
        out_transvel[3*i+0] = 0.1f * (t1.x - t0.x - fmaf(v0x, dt, dtx));
        out_transvel[3*i+1] = 0.1f * (t1.y - t0.y - fmaf(v0y, dt, dty));
        out_transvel[3*i+2] = 0.1f * (t1.z - t0.z - fmaf(v0z, dt, dtz));
    }
}

extern "C" void kernel_launch(void* const* d_in, const int* in_sizes, int n_in,
                              void* d_out, int out_size) {
    const int*   edges      = (const int*)  d_in[0];
    const float* nodes      = (const float*)d_in[1];
    const float* vels       = (const float*)d_in[2];
    const float* poses      = (const float*)d_in[3];
    const float* imu_drots  = (const float*)d_in[4];
    const float* imu_dtrans = (const float*)d_in[5];
    const float* imu_dvels  = (const float*)d_in[6];
    const float* dts        = (const float*)d_in[7];

    int E = in_sizes[0] / 2;
    int N = in_sizes[1] / 7;
    int M = N - 1;

    float* out = (float*)d_out;
    float* out_pg       = out;
    float* out_adjvel   = out + (size_t)6 * E;
    float* out_imurot   = out_adjvel + (size_t)3 * M;
    float* out_transvel = out_imurot + (size_t)3 * M;

    const int TPB = 256;
    int nEdgeThreads = (E + 1) / 2;                     // 2 edges per thread
    int edgeBlocks = (nEdgeThreads + TPB - 1) / TPB;
    int nodeBlocks = (M + TPB - 1) / TPB;

    fused_kernel<<<edgeBlocks + nodeBlocks, TPB>>>(
        edges, nodes, vels, poses, imu_drots, imu_dtrans, imu_dvels, dts,
        out_pg, out_adjvel, out_imurot, out_transvel,
        E, M, edgeBlocks);
}